// round 3
// baseline (speedup 1.0000x reference)
#include <cuda_runtime.h>
#include <cstdint>

#define N_RAYS   32768
#define MAX_S    512
#define RES_I    128
#define STEP_SZ  0.005f

// occ encoding mode: 0 = 1-byte bool, 1 = 4-byte (int32/float32), 2 = 2-byte (bf16)
__device__ int g_occ_mode;

__global__ void detect_occ_dtype_kernel(const uint32_t* __restrict__ w, int nwords)
{
    __shared__ int ev;
    if (threadIdx.x == 0) ev = 0;
    __syncthreads();

    int local = 0;
    for (int i = threadIdx.x; i < nwords; i += blockDim.x) {
        uint32_t v = w[i];
        if (v == 0u || v == 1u || v == 0x3F800000u) continue;      // ambiguous / 4-byte
        if (v == 0x00003F80u || v == 0x3F803F80u) local |= 2;       // bf16 halfword combos
        else                                      local |= 1;       // byte-bool combos
    }
    if (local) atomicOr(&ev, local);
    __syncthreads();

    if (threadIdx.x == 0) {
        int e = ev;
        g_occ_mode = (e & 1) ? 0 : ((e & 2) ? 2 : 1);
    }
}

__global__ __launch_bounds__(MAX_S)
void occgrid_march_kernel(const uint8_t* __restrict__ occ,
                          const float*   __restrict__ vecA,
                          const float*   __restrict__ vecB,
                          const int*     __restrict__ rays_bidx,
                          float*         __restrict__ out_pts,   // [N, S, 3]
                          float*         __restrict__ out_t,     // [N, S]
                          float*         __restrict__ out_mask)  // [N, S]
{
    const int ray = blockIdx.x;
    const int s   = threadIdx.x;
    const int occ_mode = g_occ_mode;

    const float ax = __ldg(&vecA[ray * 3 + 0]);
    const float ay = __ldg(&vecA[ray * 3 + 1]);
    const float az = __ldg(&vecA[ray * 3 + 2]);
    const float bx = __ldg(&vecB[ray * 3 + 0]);
    const float by = __ldg(&vecB[ray * 3 + 1]);
    const float bz = __ldg(&vecB[ray * 3 + 2]);

    // rays_d is unit-norm; rays_o has norm^2 <= 0.75. Resolve per-ray.
    const float na = ax * ax + ay * ay + az * az;
    const bool a_is_dir = fabsf(na - 1.0f) < 0.1f;

    const float ox = a_is_dir ? bx : ax;
    const float oy = a_is_dir ? by : ay;
    const float oz = a_is_dir ? bz : az;
    const float dx = a_is_dir ? ax : bx;
    const float dy = a_is_dir ? ay : by;
    const float dz = a_is_dir ? az : bz;

    const int b = __ldg(&rays_bidx[ray]);

    // safe_d / inv_d exactly as reference
    const float eps = 1e-10f;
    float sdx = (fabsf(dx) < eps) ? ((dx >= 0.0f) ? eps : -eps) : dx;
    float sdy = (fabsf(dy) < eps) ? ((dy >= 0.0f) ? eps : -eps) : dy;
    float sdz = (fabsf(dz) < eps) ? ((dz >= 0.0f) ? eps : -eps) : dz;
    float ix_ = 1.0f / sdx, iy_ = 1.0f / sdy, iz_ = 1.0f / sdz;

    float t0x = __fmul_rn(__fsub_rn(-1.0f, ox), ix_);
    float t1x = __fmul_rn(__fsub_rn( 1.0f, ox), ix_);
    float t0y = __fmul_rn(__fsub_rn(-1.0f, oy), iy_);
    float t1y = __fmul_rn(__fsub_rn( 1.0f, oy), iy_);
    float t0z = __fmul_rn(__fsub_rn(-1.0f, oz), iz_);
    float t1z = __fmul_rn(__fsub_rn( 1.0f, oz), iz_);

    float tmin = fmaxf(fmaxf(fminf(t0x, t1x), fminf(t0y, t1y)), fminf(t0z, t1z));
    float tmax = fminf(fminf(fmaxf(t0x, t1x), fmaxf(t0y, t1y)), fmaxf(t0z, t1z));
    float nearv = fmaxf(tmin, 0.0f);

    // t = near + (s + 0.5) * STEP  (round each op like jax)
    const float t = __fadd_rn(nearv, __fmul_rn((float)s + 0.5f, STEP_SZ));

    // pts = o + t * d  (mul then add, no fma — match jax rounding)
    float px = __fadd_rn(ox, __fmul_rn(t, dx));
    float py = __fadd_rn(oy, __fmul_rn(t, dy));
    float pz = __fadd_rn(oz, __fmul_rn(t, dz));

    const bool in_box = (t < tmax) && (tmax > nearv);

    bool m = false;
    if (in_box) {
        // ((p*0.5 + 0.5) * 128), truncate toward zero, clip — exact op-by-op rounding
        int gx = (int)__fmul_rn(__fadd_rn(__fmul_rn(px, 0.5f), 0.5f), (float)RES_I);
        int gy = (int)__fmul_rn(__fadd_rn(__fmul_rn(py, 0.5f), 0.5f), (float)RES_I);
        int gz = (int)__fmul_rn(__fadd_rn(__fmul_rn(pz, 0.5f), 0.5f), (float)RES_I);
        gx = min(max(gx, 0), RES_I - 1);
        gy = min(max(gy, 0), RES_I - 1);
        gz = min(max(gz, 0), RES_I - 1);
        long idx = (((long)b * RES_I + gx) * RES_I + gy) * RES_I + gz;

        if (occ_mode == 1) {
            m = (__ldg((const uint32_t*)occ + idx) != 0u);
        } else if (occ_mode == 0) {
            m = (__ldg(occ + idx) != 0);
        } else {
            m = (__ldg((const uint16_t*)occ + idx) != 0);
        }
    }

    const float mf = m ? 1.0f : 0.0f;
    const long base = (long)ray * MAX_S + s;

    out_pts[base * 3 + 0] = __fmul_rn(px, mf);
    out_pts[base * 3 + 1] = __fmul_rn(py, mf);
    out_pts[base * 3 + 2] = __fmul_rn(pz, mf);
    out_t[base]    = t;
    out_mask[base] = mf;
}

extern "C" void kernel_launch(void* const* d_in, const int* in_sizes, int n_in,
                              void* d_out, int out_size)
{
    // Classify inputs by element count (robust to metadata ordering):
    //   occ_grid  : 4*128^3 = 8388608 (largest)
    //   rays_o/d  : 98304 (two; o-vs-d resolved in-kernel by unit-norm test)
    //   rays_bidx : 32768
    //   max_steps : 1 (compile-time 512)
    const uint8_t* occ  = nullptr;
    const float*   vecA = nullptr;
    const float*   vecB = nullptr;
    const int*     bidx = nullptr;

    for (int i = 0; i < n_in; i++) {
        const int sz = in_sizes[i];
        if (sz == 4 * RES_I * RES_I * RES_I) {
            occ = (const uint8_t*)d_in[i];
        } else if (sz == N_RAYS * 3) {
            if (!vecA) vecA = (const float*)d_in[i];
            else       vecB = (const float*)d_in[i];
        } else if (sz == N_RAYS) {
            bidx = (const int*)d_in[i];
        }
    }

    float* out      = (float*)d_out;
    float* out_pts  = out;                                   // N*S*3
    float* out_t    = out + (long)N_RAYS * MAX_S * 3;        // N*S
    float* out_mask = out_t + (long)N_RAYS * MAX_S;          // N*S

    // Detect occ encoding (first 4096 words = 16 KB is plenty at 50% density)
    detect_occ_dtype_kernel<<<1, 256>>>((const uint32_t*)occ, 4096);
    occgrid_march_kernel<<<N_RAYS, MAX_S>>>(occ, vecA, vecB, bidx,
                                            out_pts, out_t, out_mask);
}

// round 4
// speedup vs baseline: 1.6049x; 1.6049x over previous
#include <cuda_runtime.h>
#include <cstdint>

#define N_RAYS   32768
#define MAX_S    512
#define RES_I    128
#define STEP_SZ  0.005f
#define SPT      4                 // samples per thread
#define TPB      (MAX_S / SPT)     // 128 threads per block (one block per ray)

// occ encoding mode: 0 = 1-byte bool, 1 = 4-byte (int32/float32), 2 = 2-byte (bf16)
__device__ int g_occ_mode;

__global__ void detect_occ_dtype_kernel(const uint32_t* __restrict__ w, int nwords)
{
    __shared__ int ev;
    if (threadIdx.x == 0) ev = 0;
    __syncthreads();

    int local = 0;
    for (int i = threadIdx.x; i < nwords; i += blockDim.x) {
        uint32_t v = w[i];
        if (v == 0u || v == 1u || v == 0x3F800000u) continue;      // ambiguous / 4-byte
        if (v == 0x00003F80u || v == 0x3F803F80u) local |= 2;       // bf16 halfword combos
        else                                      local |= 1;       // byte-bool combos
    }
    if (local) atomicOr(&ev, local);
    __syncthreads();

    if (threadIdx.x == 0) {
        int e = ev;
        g_occ_mode = (e & 1) ? 0 : ((e & 2) ? 2 : 1);
    }
}

__global__ __launch_bounds__(TPB)
void occgrid_march_kernel(const uint8_t* __restrict__ occ,
                          const float*   __restrict__ vecA,
                          const float*   __restrict__ vecB,
                          const int*     __restrict__ rays_bidx,
                          float*         __restrict__ out_pts,   // [N, S, 3]
                          float*         __restrict__ out_t,     // [N, S]
                          float*         __restrict__ out_mask)  // [N, S]
{
    const int ray = blockIdx.x;
    const int s0  = threadIdx.x * SPT;
    const int occ_mode = g_occ_mode;

    const float ax = __ldg(&vecA[ray * 3 + 0]);
    const float ay = __ldg(&vecA[ray * 3 + 1]);
    const float az = __ldg(&vecA[ray * 3 + 2]);
    const float bx = __ldg(&vecB[ray * 3 + 0]);
    const float by = __ldg(&vecB[ray * 3 + 1]);
    const float bz = __ldg(&vecB[ray * 3 + 2]);

    // rays_d is unit-norm; rays_o has norm^2 <= 0.75. Resolve per-ray.
    const float na = ax * ax + ay * ay + az * az;
    const bool a_is_dir = fabsf(na - 1.0f) < 0.1f;

    const float ox = a_is_dir ? bx : ax;
    const float oy = a_is_dir ? by : ay;
    const float oz = a_is_dir ? bz : az;
    const float dx = a_is_dir ? ax : bx;
    const float dy = a_is_dir ? ay : by;
    const float dz = a_is_dir ? az : bz;

    const int b = __ldg(&rays_bidx[ray]);
    const int occ_base = b * (RES_I * RES_I * RES_I);

    // safe_d / inv_d exactly as reference
    const float eps = 1e-10f;
    float sdx = (fabsf(dx) < eps) ? ((dx >= 0.0f) ? eps : -eps) : dx;
    float sdy = (fabsf(dy) < eps) ? ((dy >= 0.0f) ? eps : -eps) : dy;
    float sdz = (fabsf(dz) < eps) ? ((dz >= 0.0f) ? eps : -eps) : dz;
    float ix_ = 1.0f / sdx, iy_ = 1.0f / sdy, iz_ = 1.0f / sdz;

    float t0x = __fmul_rn(__fsub_rn(-1.0f, ox), ix_);
    float t1x = __fmul_rn(__fsub_rn( 1.0f, ox), ix_);
    float t0y = __fmul_rn(__fsub_rn(-1.0f, oy), iy_);
    float t1y = __fmul_rn(__fsub_rn( 1.0f, oy), iy_);
    float t0z = __fmul_rn(__fsub_rn(-1.0f, oz), iz_);
    float t1z = __fmul_rn(__fsub_rn( 1.0f, oz), iz_);

    float tmin = fmaxf(fmaxf(fminf(t0x, t1x), fminf(t0y, t1y)), fminf(t0z, t1z));
    float tmax = fminf(fminf(fmaxf(t0x, t1x), fmaxf(t0y, t1y)), fmaxf(t0z, t1z));
    float nearv = fmaxf(tmin, 0.0f);

    float pts[SPT * 3];
    float tv[SPT];
    float mv[SPT];

#pragma unroll
    for (int i = 0; i < SPT; i++) {
        const int s = s0 + i;
        // t = near + (s + 0.5) * STEP  (round each op like jax)
        const float t = __fadd_rn(nearv, __fmul_rn((float)s + 0.5f, STEP_SZ));

        // pts = o + t * d  (mul then add, no fma — match jax rounding)
        const float px = __fadd_rn(ox, __fmul_rn(t, dx));
        const float py = __fadd_rn(oy, __fmul_rn(t, dy));
        const float pz = __fadd_rn(oz, __fmul_rn(t, dz));

        const bool in_box = (t < tmax) && (tmax > nearv);

        bool m = false;
        if (in_box) {
            int gx = (int)__fmul_rn(__fadd_rn(__fmul_rn(px, 0.5f), 0.5f), (float)RES_I);
            int gy = (int)__fmul_rn(__fadd_rn(__fmul_rn(py, 0.5f), 0.5f), (float)RES_I);
            int gz = (int)__fmul_rn(__fadd_rn(__fmul_rn(pz, 0.5f), 0.5f), (float)RES_I);
            gx = min(max(gx, 0), RES_I - 1);
            gy = min(max(gy, 0), RES_I - 1);
            gz = min(max(gz, 0), RES_I - 1);
            const int idx = occ_base + ((gx * RES_I + gy) * RES_I + gz);

            if (occ_mode == 1)      m = (__ldg((const uint32_t*)occ + idx) != 0u);
            else if (occ_mode == 0) m = (__ldg(occ + idx) != 0);
            else                    m = (__ldg((const uint16_t*)occ + idx) != 0);
        }

        const float mf = m ? 1.0f : 0.0f;
        pts[i * 3 + 0] = __fmul_rn(px, mf);
        pts[i * 3 + 1] = __fmul_rn(py, mf);
        pts[i * 3 + 2] = __fmul_rn(pz, mf);
        tv[i] = t;
        mv[i] = mf;
    }

    // base = ray*512 + s0; s0 % 4 == 0 -> all vector stores 16B-aligned
    const int base = ray * MAX_S + s0;

    float4* pp = (float4*)(out_pts + base * 3);     // 48 B = 3x float4
    __stcs(pp + 0, make_float4(pts[0], pts[1], pts[2],  pts[3]));
    __stcs(pp + 1, make_float4(pts[4], pts[5], pts[6],  pts[7]));
    __stcs(pp + 2, make_float4(pts[8], pts[9], pts[10], pts[11]));
    __stcs((float4*)(out_t + base),    make_float4(tv[0], tv[1], tv[2], tv[3]));
    __stcs((float4*)(out_mask + base), make_float4(mv[0], mv[1], mv[2], mv[3]));
}

extern "C" void kernel_launch(void* const* d_in, const int* in_sizes, int n_in,
                              void* d_out, int out_size)
{
    // Classify inputs by element count (robust to metadata ordering):
    //   occ_grid  : 4*128^3 = 8388608 (largest)
    //   rays_o/d  : 98304 (two; o-vs-d resolved in-kernel by unit-norm test)
    //   rays_bidx : 32768
    //   max_steps : 1 (compile-time 512)
    const uint8_t* occ  = nullptr;
    const float*   vecA = nullptr;
    const float*   vecB = nullptr;
    const int*     bidx = nullptr;

    for (int i = 0; i < n_in; i++) {
        const int sz = in_sizes[i];
        if (sz == 4 * RES_I * RES_I * RES_I) {
            occ = (const uint8_t*)d_in[i];
        } else if (sz == N_RAYS * 3) {
            if (!vecA) vecA = (const float*)d_in[i];
            else       vecB = (const float*)d_in[i];
        } else if (sz == N_RAYS) {
            bidx = (const int*)d_in[i];
        }
    }

    float* out      = (float*)d_out;
    float* out_pts  = out;                                   // N*S*3
    float* out_t    = out + (long)N_RAYS * MAX_S * 3;        // N*S
    float* out_mask = out_t + (long)N_RAYS * MAX_S;          // N*S

    detect_occ_dtype_kernel<<<1, 128>>>((const uint32_t*)occ, 1024);
    occgrid_march_kernel<<<N_RAYS, TPB>>>(occ, vecA, vecB, bidx,
                                          out_pts, out_t, out_mask);
}